// round 16
// baseline (speedup 1.0000x reference)
#include <cuda_runtime.h>
#include <cstdint>

#define NUM_IN 25
#define NUM_OUT 20
#define TILE_M 128
#define XS 37            // smem row stride (floats): 5 ⊥ 32 -> conflict-free stores

typedef unsigned long long u64;

struct CB { float b1[32]; float b2[32]; };
__constant__ CB cB;

// Pre-arranged B fragments for mma.m16n8k8 (row.col), float2 {b0,b1} per lane.
// Layer1: [kt*4+nt][lane], 16 tiles. Layer2: [kt*3+nt][lane], 12 tiles.
__device__ __align__(16) float2 gB1h[512], gB1l[512];
__device__ __align__(16) float2 gB2h[384], gB2l[384];

__device__ __forceinline__ float t32f(float v) {
    uint32_t r;
    asm("cvt.rna.tf32.f32 %0, %1;" : "=r"(r) : "f"(v));
    return __uint_as_float(r);
}

__device__ __forceinline__ void mma8(float* d, const uint32_t* a, float2 b) {
    asm volatile(
        "mma.sync.aligned.m16n8k8.row.col.f32.tf32.tf32.f32 "
        "{%0,%1,%2,%3}, {%4,%5,%6,%7}, {%8,%9}, {%0,%1,%2,%3};"
        : "+f"(d[0]), "+f"(d[1]), "+f"(d[2]), "+f"(d[3])
        : "r"(a[0]), "r"(a[1]), "r"(a[2]), "r"(a[3]),
          "r"(__float_as_uint(b.x)), "r"(__float_as_uint(b.y)));
}

// ---- Prep: biases -> cB ; W1/W2 tf32-split as per-lane B fragments ----
__global__ void prep_kernel(CB* cb,
                            const float* __restrict__ W1, const float* __restrict__ b1,
                            const float* __restrict__ W2, const float* __restrict__ b2)
{
    int t = threadIdx.x;
    // Layer-1 fragments: 16 tiles (kt 0..3, nt 0..3) x 32 lanes
    for (int i = t; i < 512; i += blockDim.x) {
        int lane = i & 31, tile = i >> 5;
        int nt = tile & 3, kt = tile >> 2;
        int gq = lane >> 2, tig = lane & 3;
        int n = nt * 8 + gq;
        int k0 = kt * 8 + tig, k1 = k0 + 4;
        float w0 = (n < NUM_IN && k0 < NUM_IN) ? W1[n * NUM_IN + k0] : 0.0f;
        float w1 = (n < NUM_IN && k1 < NUM_IN) ? W1[n * NUM_IN + k1] : 0.0f;
        float h0 = t32f(w0), h1 = t32f(w1);
        gB1h[i] = make_float2(h0, h1);
        gB1l[i] = make_float2(t32f(w0 - h0), t32f(w1 - h1));
    }
    // Layer-2 fragments: 12 tiles (kt 0..3, nt 0..2) x 32 lanes
    for (int i = t; i < 384; i += blockDim.x) {
        int lane = i & 31, tile = i >> 5;
        int nt = tile % 3, kt = tile / 3;
        int gq = lane >> 2, tig = lane & 3;
        int n = nt * 8 + gq;
        int k0 = kt * 8 + tig, k1 = k0 + 4;
        float w0 = (n < NUM_OUT && k0 < NUM_IN) ? W2[n * NUM_IN + k0] : 0.0f;
        float w1 = (n < NUM_OUT && k1 < NUM_IN) ? W2[n * NUM_IN + k1] : 0.0f;
        float h0 = t32f(w0), h1 = t32f(w1);
        gB2h[i] = make_float2(h0, h1);
        gB2l[i] = make_float2(t32f(w0 - h0), t32f(w1 - h1));
    }
    if (t < 32) cb->b1[t] = (t < NUM_IN) ? b1[t] : 0.0f;
    if (t < 32) cb->b2[t] = (t < NUM_OUT) ? b2[t] : 0.0f;
}

__global__ void __launch_bounds__(128)
mlp_mma_kernel(const float* __restrict__ r,
               const float* __restrict__ a_data,
               const float* __restrict__ a_material,
               const float* __restrict__ a_influx,
               const float* __restrict__ b_data,
               const float* __restrict__ b_material,
               const float* __restrict__ b_influx,
               const float* __restrict__ e_data,
               float* __restrict__ out,
               int E)
{
    __shared__ float xh[TILE_M * XS];
    __shared__ float xl[TILE_M * XS];

    const int tid = threadIdx.x;
    const int lane = tid & 31, warp = tid >> 5;
    const int gq = lane >> 2, tig = lane & 3;
    const int rb = warp * 32;   // this warp's row band [rb, rb+32)

    // ---- Gather this edge's 25 features (clamped), pad to 32 ----
    long e = (long)blockIdx.x * TILE_M + tid;
    long el = (e < E) ? e : (long)(E - 1);
    const float4* ad4 = reinterpret_cast<const float4*>(a_data);
    const float4* bd4 = reinterpret_cast<const float4*>(b_data);
    const float4* ed4 = reinterpret_cast<const float4*>(e_data);

    float x[32];
    x[0] = r[el];
    { float4 p = ad4[2*el];   x[1]=p.x; x[2]=p.y; x[3]=p.z; x[4]=p.w; }
    { float4 p = ad4[2*el+1]; x[5]=p.x; x[6]=p.y; x[7]=p.z; x[8]=p.w; }
    x[9]  = a_material[el];
    x[10] = a_influx[el];
    { float4 p = bd4[2*el];   x[11]=p.x; x[12]=p.y; x[13]=p.z; x[14]=p.w; }
    { float4 p = bd4[2*el+1]; x[15]=p.x; x[16]=p.y; x[17]=p.z; x[18]=p.w; }
    x[19] = b_material[el];
    x[20] = b_influx[el];
    { float4 p = ed4[el];     x[21]=p.x; x[22]=p.y; x[23]=p.z; x[24]=p.w; }
    #pragma unroll
    for (int k = NUM_IN; k < 32; k++) x[k] = 0.0f;

    // ---- tf32-split store: row = tid ----
    #pragma unroll
    for (int c = 0; c < 32; c++) {
        float h = t32f(x[c]);
        xh[tid * XS + c] = h;
        xl[tid * XS + c] = t32f(x[c] - h);
    }
    __syncthreads();

    // ================= Layer 1: D1[128,32] = X @ W1^T =================
    float d1[2][4][4];
    #pragma unroll
    for (int mt = 0; mt < 2; mt++)
        #pragma unroll
        for (int nt = 0; nt < 4; nt++)
            #pragma unroll
            for (int i = 0; i < 4; i++) d1[mt][nt][i] = 0.0f;

    #pragma unroll
    for (int kt = 0; kt < 4; kt++) {
        uint32_t ah[2][4], al[2][4];
        #pragma unroll
        for (int mt = 0; mt < 2; mt++) {
            int base = (rb + mt * 16 + gq) * XS + kt * 8 + tig;
            ah[mt][0] = __float_as_uint(xh[base]);
            ah[mt][1] = __float_as_uint(xh[base + 8 * XS]);
            ah[mt][2] = __float_as_uint(xh[base + 4]);
            ah[mt][3] = __float_as_uint(xh[base + 8 * XS + 4]);
            al[mt][0] = __float_as_uint(xl[base]);
            al[mt][1] = __float_as_uint(xl[base + 8 * XS]);
            al[mt][2] = __float_as_uint(xl[base + 4]);
            al[mt][3] = __float_as_uint(xl[base + 8 * XS + 4]);
        }
        float2 bh[4], bl[4];
        #pragma unroll
        for (int nt = 0; nt < 4; nt++) {
            bh[nt] = __ldg(&gB1h[(kt * 4 + nt) * 32 + lane]);
            bl[nt] = __ldg(&gB1l[(kt * 4 + nt) * 32 + lane]);
        }
        #pragma unroll
        for (int mt = 0; mt < 2; mt++)
            #pragma unroll
            for (int nt = 0; nt < 4; nt++) {
                mma8(d1[mt][nt], ah[mt], bh[nt]);   // hi*hi
                mma8(d1[mt][nt], ah[mt], bl[nt]);   // hi*lo
                mma8(d1[mt][nt], al[mt], bh[nt]);   // lo*hi
            }
    }

    // ---- Epilogue 1: y = relu(D1 + b1), split, rewrite own rows ----
    const float2* b1v = reinterpret_cast<const float2*>(cB.b1);
    #pragma unroll
    for (int mt = 0; mt < 2; mt++) {
        int r0 = rb + mt * 16 + gq;
        int r1 = r0 + 8;
        #pragma unroll
        for (int nt = 0; nt < 4; nt++) {
            int co = nt * 8 + tig * 2;
            float2 bb = b1v[co >> 1];
            float v00 = fmaxf(d1[mt][nt][0] + bb.x, 0.0f);
            float v01 = fmaxf(d1[mt][nt][1] + bb.y, 0.0f);
            float v10 = fmaxf(d1[mt][nt][2] + bb.x, 0.0f);
            float v11 = fmaxf(d1[mt][nt][3] + bb.y, 0.0f);
            float h;
            h = t32f(v00); xh[r0 * XS + co]     = h; xl[r0 * XS + co]     = t32f(v00 - h);
            h = t32f(v01); xh[r0 * XS + co + 1] = h; xl[r0 * XS + co + 1] = t32f(v01 - h);
            h = t32f(v10); xh[r1 * XS + co]     = h; xl[r1 * XS + co]     = t32f(v10 - h);
            h = t32f(v11); xh[r1 * XS + co + 1] = h; xl[r1 * XS + co + 1] = t32f(v11 - h);
        }
    }
    __syncwarp();

    // ================= Layer 2: D2[128,24] = Y @ W2^T =================
    float d2[2][3][4];
    #pragma unroll
    for (int mt = 0; mt < 2; mt++)
        #pragma unroll
        for (int nt = 0; nt < 3; nt++)
            #pragma unroll
            for (int i = 0; i < 4; i++) d2[mt][nt][i] = 0.0f;

    #pragma unroll
    for (int kt = 0; kt < 4; kt++) {
        uint32_t ah[2][4], al[2][4];
        #pragma unroll
        for (int mt = 0; mt < 2; mt++) {
            int base = (rb + mt * 16 + gq) * XS + kt * 8 + tig;
            ah[mt][0] = __float_as_uint(xh[base]);
            ah[mt][1] = __float_as_uint(xh[base + 8 * XS]);
            ah[mt][2] = __float_as_uint(xh[base + 4]);
            ah[mt][3] = __float_as_uint(xh[base + 8 * XS + 4]);
            al[mt][0] = __float_as_uint(xl[base]);
            al[mt][1] = __float_as_uint(xl[base + 8 * XS]);
            al[mt][2] = __float_as_uint(xl[base + 4]);
            al[mt][3] = __float_as_uint(xl[base + 8 * XS + 4]);
        }
        float2 bh[3], bl[3];
        #pragma unroll
        for (int nt = 0; nt < 3; nt++) {
            bh[nt] = __ldg(&gB2h[(kt * 3 + nt) * 32 + lane]);
            bl[nt] = __ldg(&gB2l[(kt * 3 + nt) * 32 + lane]);
        }
        #pragma unroll
        for (int mt = 0; mt < 2; mt++)
            #pragma unroll
            for (int nt = 0; nt < 3; nt++) {
                mma8(d2[mt][nt], ah[mt], bh[nt]);
                mma8(d2[mt][nt], ah[mt], bl[nt]);
                mma8(d2[mt][nt], al[mt], bh[nt]);
            }
    }

    // ---- Epilogue 2: z = relu(D2 + b2) -> out (3 concatenated blocks) ----
    const float2* b2v = reinterpret_cast<const float2*>(cB.b2);
    float2* ov2 = reinterpret_cast<float2*>(out);
    long E4 = 4L * (long)E;   // float2 units per 8-wide block
    long E8 = 8L * (long)E;

    #pragma unroll
    for (int mt = 0; mt < 2; mt++) {
        long er0 = (long)blockIdx.x * TILE_M + rb + mt * 16 + gq;
        long er1 = er0 + 8;
        #pragma unroll
        for (int nt = 0; nt < 3; nt++) {
            int co = nt * 8 + tig * 2;
            if (nt == 2 && co >= 20) continue;   // cols 20..23 are padding
            float2 bb = b2v[co >> 1];
            float2 z0 = make_float2(fmaxf(d2[mt][nt][0] + bb.x, 0.0f),
                                    fmaxf(d2[mt][nt][1] + bb.y, 0.0f));
            float2 z1 = make_float2(fmaxf(d2[mt][nt][2] + bb.x, 0.0f),
                                    fmaxf(d2[mt][nt][3] + bb.y, 0.0f));
            long i0, i1;
            if (co < 8) {
                i0 = er0 * 4 + (co >> 1);
                i1 = er1 * 4 + (co >> 1);
            } else if (co < 16) {
                i0 = E4 + er0 * 4 + ((co - 8) >> 1);
                i1 = E4 + er1 * 4 + ((co - 8) >> 1);
            } else {
                i0 = E8 + er0 * 2 + ((co - 16) >> 1);
                i1 = E8 + er1 * 2 + ((co - 16) >> 1);
            }
            if (er0 < E) ov2[i0] = z0;
            if (er1 < E) ov2[i1] = z1;
        }
    }
}

extern "C" void kernel_launch(void* const* d_in, const int* in_sizes, int n_in,
                              void* d_out, int out_size)
{
    const float* r          = (const float*)d_in[0];
    const float* a_data     = (const float*)d_in[1];
    const float* a_material = (const float*)d_in[2];
    const float* a_influx   = (const float*)d_in[3];
    const float* b_data     = (const float*)d_in[4];
    const float* b_material = (const float*)d_in[5];
    const float* b_influx   = (const float*)d_in[6];
    const float* e_data     = (const float*)d_in[7];
    const float* W1         = (const float*)d_in[8];
    const float* b1         = (const float*)d_in[9];
    const float* W2         = (const float*)d_in[10];
    const float* b2         = (const float*)d_in[11];
    float* out = (float*)d_out;

    int E = in_sizes[0];

    void* cb_addr = nullptr;
    cudaGetSymbolAddress(&cb_addr, cB);
    prep_kernel<<<1, 256>>>((CB*)cb_addr, W1, b1, W2, b2);

    int blocks = (E + TILE_M - 1) / TILE_M;
    mlp_mma_kernel<<<blocks, TILE_M>>>(r, a_data, a_material, a_influx,
                                       b_data, b_material, b_influx, e_data,
                                       out, E);
}

// round 17
// speedup vs baseline: 1.8263x; 1.8263x over previous
#include <cuda_runtime.h>
#include <cuda_fp16.h>
#include <cstdint>

#define NUM_IN 25
#define NUM_OUT 20
#define TILE_M 128
#define ROWH 40          // halves per smem row (80B): conflict-free ldmatrix phases

struct CB { float b1[32]; float b2[32]; };
__constant__ CB cB;

// Pre-packed B fragments for mma.m16n8k16 f16 (row.col): uint2 {b0pair, b1pair} per lane.
// Layer1: tiles (kt 0..1, nt 0..3) -> [kt*4+nt][lane]. Layer2: (kt 0..1, nt 0..2).
__device__ __align__(16) uint2 gB1h[256], gB1l[256];
__device__ __align__(16) uint2 gB2h[192], gB2l[192];

__device__ __forceinline__ uint32_t pack2(__half a, __half b) {
    return (uint32_t)__half_as_ushort(a) | ((uint32_t)__half_as_ushort(b) << 16);
}

__device__ __forceinline__ void mma16(float* d, const uint32_t* a, uint2 b) {
    asm volatile(
        "mma.sync.aligned.m16n8k16.row.col.f32.f16.f16.f32 "
        "{%0,%1,%2,%3}, {%4,%5,%6,%7}, {%8,%9}, {%0,%1,%2,%3};"
        : "+f"(d[0]), "+f"(d[1]), "+f"(d[2]), "+f"(d[3])
        : "r"(a[0]), "r"(a[1]), "r"(a[2]), "r"(a[3]), "r"(b.x), "r"(b.y));
}

__device__ __forceinline__ void ldsm4(uint32_t addr, uint32_t* f) {
    asm volatile("ldmatrix.sync.aligned.m8n8.x4.shared.b16 {%0,%1,%2,%3}, [%4];"
                 : "=r"(f[0]), "=r"(f[1]), "=r"(f[2]), "=r"(f[3]) : "r"(addr));
}

// ---- Prep: biases -> cB ; W1/W2 fp16-split per-lane B fragments ----
__global__ void prep_kernel(CB* cb,
                            const float* __restrict__ W1, const float* __restrict__ b1,
                            const float* __restrict__ W2, const float* __restrict__ b2)
{
    int t = threadIdx.x;
    // Layer 1: 8 tiles x 32 lanes
    for (int i = t; i < 256; i += blockDim.x) {
        int lane = i & 31, tile = i >> 5;
        int kt = tile >> 2, nt = tile & 3;
        int gq = lane >> 2, tig = lane & 3;
        int n = nt * 8 + gq;
        int k0 = kt * 16 + tig * 2;
        float w[4];
        #pragma unroll
        for (int j = 0; j < 4; j++) {
            int k = k0 + (j >> 1) * 8 + (j & 1);
            w[j] = (n < NUM_IN && k < NUM_IN) ? W1[n * NUM_IN + k] : 0.0f;
        }
        __half h[4], l[4];
        #pragma unroll
        for (int j = 0; j < 4; j++) {
            h[j] = __float2half_rn(w[j]);
            l[j] = __float2half_rn(w[j] - __half2float(h[j]));
        }
        gB1h[i] = make_uint2(pack2(h[0], h[1]), pack2(h[2], h[3]));
        gB1l[i] = make_uint2(pack2(l[0], l[1]), pack2(l[2], l[3]));
    }
    // Layer 2: 6 tiles x 32 lanes
    for (int i = t; i < 192; i += blockDim.x) {
        int lane = i & 31, tile = i >> 5;
        int kt = tile / 3, nt = tile % 3;
        int gq = lane >> 2, tig = lane & 3;
        int n = nt * 8 + gq;
        int k0 = kt * 16 + tig * 2;
        float w[4];
        #pragma unroll
        for (int j = 0; j < 4; j++) {
            int k = k0 + (j >> 1) * 8 + (j & 1);
            w[j] = (n < NUM_OUT && k < NUM_IN) ? W2[n * NUM_IN + k] : 0.0f;
        }
        __half h[4], l[4];
        #pragma unroll
        for (int j = 0; j < 4; j++) {
            h[j] = __float2half_rn(w[j]);
            l[j] = __float2half_rn(w[j] - __half2float(h[j]));
        }
        gB2h[i] = make_uint2(pack2(h[0], h[1]), pack2(h[2], h[3]));
        gB2l[i] = make_uint2(pack2(l[0], l[1]), pack2(l[2], l[3]));
    }
    if (t < 32) cb->b1[t] = (t < NUM_IN) ? b1[t] : 0.0f;
    if (t < 32) cb->b2[t] = (t < NUM_OUT) ? b2[t] : 0.0f;
}

__global__ void __launch_bounds__(128)
mlp_mma_kernel(const float* __restrict__ r,
               const float* __restrict__ a_data,
               const float* __restrict__ a_material,
               const float* __restrict__ a_influx,
               const float* __restrict__ b_data,
               const float* __restrict__ b_material,
               const float* __restrict__ b_influx,
               const float* __restrict__ e_data,
               float* __restrict__ out,
               int E)
{
    __shared__ __align__(16) __half sXh[TILE_M * ROWH];
    __shared__ __align__(16) __half sXl[TILE_M * ROWH];

    const int tid = threadIdx.x;
    const int lane = tid & 31, warp = tid >> 5;
    const int gq = lane >> 2, tig = lane & 3;
    const int rb = warp * 32;

    const uint32_t baseH = (uint32_t)__cvta_generic_to_shared(sXh);
    const uint32_t baseL = (uint32_t)__cvta_generic_to_shared(sXl);
    // ldmatrix lane address components
    const int lrow = ((lane >> 3) & 1) * 8 + (lane & 7);
    const int lkb  = (lane >> 4) * 16;          // k-col byte offset within tile

    // ---- Gather this edge's 25 features (clamped), pad to 32 ----
    long e = (long)blockIdx.x * TILE_M + tid;
    long el = (e < E) ? e : (long)(E - 1);
    const float4* ad4 = reinterpret_cast<const float4*>(a_data);
    const float4* bd4 = reinterpret_cast<const float4*>(b_data);
    const float4* ed4 = reinterpret_cast<const float4*>(e_data);

    float x[32];
    x[0] = r[el];
    { float4 p = ad4[2*el];   x[1]=p.x; x[2]=p.y; x[3]=p.z; x[4]=p.w; }
    { float4 p = ad4[2*el+1]; x[5]=p.x; x[6]=p.y; x[7]=p.z; x[8]=p.w; }
    x[9]  = a_material[el];
    x[10] = a_influx[el];
    { float4 p = bd4[2*el];   x[11]=p.x; x[12]=p.y; x[13]=p.z; x[14]=p.w; }
    { float4 p = bd4[2*el+1]; x[15]=p.x; x[16]=p.y; x[17]=p.z; x[18]=p.w; }
    x[19] = b_material[el];
    x[20] = b_influx[el];
    { float4 p = ed4[el];     x[21]=p.x; x[22]=p.y; x[23]=p.z; x[24]=p.w; }
    #pragma unroll
    for (int k = NUM_IN; k < 32; k++) x[k] = 0.0f;

    // ---- fp16-split, store row tid as 8 uint2 per buffer ----
    {
        uint2* rowH = reinterpret_cast<uint2*>(sXh + tid * ROWH);
        uint2* rowL = reinterpret_cast<uint2*>(sXl + tid * ROWH);
        #pragma unroll
        for (int g = 0; g < 8; g++) {
            __half h0 = __float2half_rn(x[4*g]),   h1 = __float2half_rn(x[4*g+1]);
            __half h2 = __float2half_rn(x[4*g+2]), h3 = __float2half_rn(x[4*g+3]);
            rowH[g] = make_uint2(pack2(h0, h1), pack2(h2, h3));
            __half l0 = __float2half_rn(x[4*g]   - __half2float(h0));
            __half l1 = __float2half_rn(x[4*g+1] - __half2float(h1));
            __half l2 = __float2half_rn(x[4*g+2] - __half2float(h2));
            __half l3 = __float2half_rn(x[4*g+3] - __half2float(h3));
            rowL[g] = make_uint2(pack2(l0, l1), pack2(l2, l3));
        }
    }
    __syncwarp();   // band rows are warp-private

    // ================= Layer 1: D1[128,32] = X @ W1^T =================
    float d1[2][4][4];
    #pragma unroll
    for (int mt = 0; mt < 2; mt++)
        #pragma unroll
        for (int nt = 0; nt < 4; nt++)
            #pragma unroll
            for (int i = 0; i < 4; i++) d1[mt][nt][i] = 0.0f;

    #pragma unroll
    for (int kt = 0; kt < 2; kt++) {
        uint32_t ah[2][4], al[2][4];
        #pragma unroll
        for (int mt = 0; mt < 2; mt++) {
            uint32_t off = (uint32_t)(rb + mt * 16 + lrow) * (ROWH * 2) + kt * 32 + lkb;
            ldsm4(baseH + off, ah[mt]);
            ldsm4(baseL + off, al[mt]);
        }
        uint2 bh[4], bl[4];
        #pragma unroll
        for (int nt = 0; nt < 4; nt++) {
            bh[nt] = __ldg(&gB1h[(kt * 4 + nt) * 32 + lane]);
            bl[nt] = __ldg(&gB1l[(kt * 4 + nt) * 32 + lane]);
        }
        #pragma unroll
        for (int mt = 0; mt < 2; mt++)
            #pragma unroll
            for (int nt = 0; nt < 4; nt++) {
                mma16(d1[mt][nt], ah[mt], bh[nt]);
                mma16(d1[mt][nt], ah[mt], bl[nt]);
                mma16(d1[mt][nt], al[mt], bh[nt]);
            }
    }

    // ---- Epilogue 1: y = relu(D1 + b1); fp16-split back into own rows ----
    const float2* b1v = reinterpret_cast<const float2*>(cB.b1);
    #pragma unroll
    for (int mt = 0; mt < 2; mt++) {
        int r0 = rb + mt * 16 + gq;
        int r1 = r0 + 8;
        #pragma unroll
        for (int nt = 0; nt < 4; nt++) {
            int co = nt * 8 + tig * 2;
            float2 bb = b1v[co >> 1];
            float v00 = fmaxf(d1[mt][nt][0] + bb.x, 0.0f);
            float v01 = fmaxf(d1[mt][nt][1] + bb.y, 0.0f);
            float v10 = fmaxf(d1[mt][nt][2] + bb.x, 0.0f);
            float v11 = fmaxf(d1[mt][nt][3] + bb.y, 0.0f);
            __half h00 = __float2half_rn(v00), h01 = __float2half_rn(v01);
            __half h10 = __float2half_rn(v10), h11 = __float2half_rn(v11);
            *reinterpret_cast<uint32_t*>(sXh + r0 * ROWH + co) = pack2(h00, h01);
            *reinterpret_cast<uint32_t*>(sXh + r1 * ROWH + co) = pack2(h10, h11);
            __half l00 = __float2half_rn(v00 - __half2float(h00));
            __half l01 = __float2half_rn(v01 - __half2float(h01));
            __half l10 = __float2half_rn(v10 - __half2float(h10));
            __half l11 = __float2half_rn(v11 - __half2float(h11));
            *reinterpret_cast<uint32_t*>(sXl + r0 * ROWH + co) = pack2(l00, l01);
            *reinterpret_cast<uint32_t*>(sXl + r1 * ROWH + co) = pack2(l10, l11);
        }
    }
    __syncwarp();

    // ================= Layer 2: D2[128,24] = Y @ W2^T =================
    float d2[2][3][4];
    #pragma unroll
    for (int mt = 0; mt < 2; mt++)
        #pragma unroll
        for (int nt = 0; nt < 3; nt++)
            #pragma unroll
            for (int i = 0; i < 4; i++) d2[mt][nt][i] = 0.0f;

    #pragma unroll
    for (int kt = 0; kt < 2; kt++) {
        uint32_t ah[2][4], al[2][4];
        #pragma unroll
        for (int mt = 0; mt < 2; mt++) {
            uint32_t off = (uint32_t)(rb + mt * 16 + lrow) * (ROWH * 2) + kt * 32 + lkb;
            ldsm4(baseH + off, ah[mt]);
            ldsm4(baseL + off, al[mt]);
        }
        uint2 bh[3], bl[3];
        #pragma unroll
        for (int nt = 0; nt < 3; nt++) {
            bh[nt] = __ldg(&gB2h[(kt * 3 + nt) * 32 + lane]);
            bl[nt] = __ldg(&gB2l[(kt * 3 + nt) * 32 + lane]);
        }
        #pragma unroll
        for (int mt = 0; mt < 2; mt++)
            #pragma unroll
            for (int nt = 0; nt < 3; nt++) {
                mma16(d2[mt][nt], ah[mt], bh[nt]);
                mma16(d2[mt][nt], ah[mt], bl[nt]);
                mma16(d2[mt][nt], al[mt], bh[nt]);
            }
    }

    // ---- Epilogue 2: z = relu(D2 + b2) -> out (3 concatenated blocks) ----
    const float2* b2v = reinterpret_cast<const float2*>(cB.b2);
    float2* ov2 = reinterpret_cast<float2*>(out);
    long E4 = 4L * (long)E;
    long E8 = 8L * (long)E;

    #pragma unroll
    for (int mt = 0; mt < 2; mt++) {
        long er0 = (long)blockIdx.x * TILE_M + rb + mt * 16 + gq;
        long er1 = er0 + 8;
        #pragma unroll
        for (int nt = 0; nt < 3; nt++) {
            int co = nt * 8 + tig * 2;
            if (nt == 2 && co >= 20) continue;   // cols 20..23 are padding
            float2 bb = b2v[co >> 1];
            float2 z0 = make_float2(fmaxf(d2[mt][nt][0] + bb.x, 0.0f),
                                    fmaxf(d2[mt][nt][1] + bb.y, 0.0f));
            float2 z1 = make_float2(fmaxf(d2[mt][nt][2] + bb.x, 0.0f),
                                    fmaxf(d2[mt][nt][3] + bb.y, 0.0f));
            long i0, i1;
            if (co < 8) {
                i0 = er0 * 4 + (co >> 1);
                i1 = er1 * 4 + (co >> 1);
            } else if (co < 16) {
                i0 = E4 + er0 * 4 + ((co - 8) >> 1);
                i1 = E4 + er1 * 4 + ((co - 8) >> 1);
            } else {
                i0 = E8 + er0 * 2 + ((co - 16) >> 1);
                i1 = E8 + er1 * 2 + ((co - 16) >> 1);
            }
            if (er0 < E) ov2[i0] = z0;
            if (er1 < E) ov2[i1] = z1;
        }
    }
}

extern "C" void kernel_launch(void* const* d_in, const int* in_sizes, int n_in,
                              void* d_out, int out_size)
{
    const float* r          = (const float*)d_in[0];
    const float* a_data     = (const float*)d_in[1];
    const float* a_material = (const float*)d_in[2];
    const float* a_influx   = (const float*)d_in[3];
    const float* b_data     = (const float*)d_in[4];
    const float* b_material = (const float*)d_in[5];
    const float* b_influx   = (const float*)d_in[6];
    const float* e_data     = (const float*)d_in[7];
    const float* W1         = (const float*)d_in[8];
    const float* b1         = (const float*)d_in[9];
    const float* W2         = (const float*)d_in[10];
    const float* b2         = (const float*)d_in[11];
    float* out = (float*)d_out;

    int E = in_sizes[0];

    void* cb_addr = nullptr;
    cudaGetSymbolAddress(&cb_addr, cB);
    prep_kernel<<<1, 256>>>((CB*)cb_addr, W1, b1, W2, b2);

    int blocks = (E + TILE_M - 1) / TILE_M;
    mlp_mma_kernel<<<blocks, TILE_M>>>(r, a_data, a_material, a_influx,
                                       b_data, b_material, b_influx, e_data,
                                       out, E);
}